// round 1
// baseline (speedup 1.0000x reference)
#include <cuda_runtime.h>
#include <math.h>

#define DB 2
#define DC 8
#define DN 16384
#define DD 256
#define DH 64
#define DW 64
#define ROWS (DB*DN)

// ---------------- scratch (__device__ globals: allocation-free rule) ----------------
__device__ float g_qn  [ROWS*DD];   // layernormed queries
__device__ float g_qt  [ROWS*DD];   // qn @ (Wq Wk^T)
__device__ float g_qbk [ROWS];      // q . bk per row
__device__ float g_sbar[ROWS*DD];   // attn-weighted sampled vectors
__device__ float g_asum[ROWS];      // sum of attn weights
__device__ float g_WkT [DD*DD];     // Wk transposed (Wkv[:, :D]^T)
__device__ float g_M   [DD*DD];     // Wq @ Wk^T
__device__ float g_W2  [DD*DD];     // Wv @ Wo
__device__ float g_v1  [DD];        // bq @ Wk^T
__device__ float g_u   [DD];        // Wq @ bk
__device__ float g_wb2 [DD];        // bv @ Wo
__device__ float g_c0;              // bq . bk

typedef unsigned long long u64;

#define FMA2(d,a,b) asm("fma.rn.f32x2 %0, %1, %2, %0;" : "+l"(d) : "l"(a), "l"(b))

__device__ __forceinline__ void unpack2(u64 v, float& lo, float& hi) {
    unsigned int l, h;
    asm("mov.b64 {%0, %1}, %2;" : "=r"(l), "=r"(h) : "l"(v));
    lo = __uint_as_float(l); hi = __uint_as_float(h);
}
__device__ __forceinline__ u64 pack2(float a, float b) {
    u64 d;
    asm("mov.b64 %0, {%1, %2};" : "=l"(d)
        : "r"(__float_as_uint(a)), "r"(__float_as_uint(b)));
    return d;
}
__device__ __forceinline__ float4 ld4(const float* p) { return *(const float4*)p; }

// ---------------- tiny precompute: u, v1, wb2, c0 ----------------
__global__ void k_vec(const float* __restrict__ Wq, const float* __restrict__ bq,
                      const float* __restrict__ Wkv, const float* __restrict__ bkv,
                      const float* __restrict__ Wo)
{
    int t = threadIdx.x;
    float au = 0.f, av = 0.f, aw = 0.f;
    for (int d = 0; d < DD; d++) {
        au += Wq[t*DD + d]      * bkv[d];        // u_e = sum_d Wq[e,d] bk_d
        av += bq[d]             * Wkv[t*(2*DD) + d]; // v1_f = sum_d bq_d Wk[f,d]
        aw += bkv[DD + d]       * Wo[d*DD + t];  // wb2_t = sum_f bv_f Wo[f,t]
    }
    g_u[t] = au; g_v1[t] = av; g_wb2[t] = aw;
    if (t == 0) {
        float c = 0.f;
        for (int d = 0; d < DD; d++) c += bq[d]*bkv[d];
        g_c0 = c;
    }
}

// ---------------- transpose Wk slice: g_WkT[d*256+f] = Wkv[f*512+d] ----------------
__global__ void k_tr(const float* __restrict__ Wkv)
{
    int idx = blockIdx.x*256 + threadIdx.x;
    int f = idx >> 8, d = idx & 255;
    g_WkT[d*DD + f] = Wkv[f*(2*DD) + d];
}

// ---------------- layernorm + qbk ----------------
__global__ __launch_bounds__(256) void k_ln(const float* __restrict__ q,
                                            const float* __restrict__ gamma,
                                            const float* __restrict__ beta)
{
    int gw   = (blockIdx.x*256 + threadIdx.x) >> 5;
    int lane = threadIdx.x & 31;
    const float* row = q + (size_t)gw*DD;
    float4 x0 = ld4(row + lane*4);
    float4 x1 = ld4(row + 128 + lane*4);
    float s  = x0.x+x0.y+x0.z+x0.w + x1.x+x1.y+x1.z+x1.w;
    float ss = x0.x*x0.x+x0.y*x0.y+x0.z*x0.z+x0.w*x0.w
             + x1.x*x1.x+x1.y*x1.y+x1.z*x1.z+x1.w*x1.w;
#pragma unroll
    for (int off = 16; off; off >>= 1) {
        s  += __shfl_xor_sync(0xffffffffu, s,  off);
        ss += __shfl_xor_sync(0xffffffffu, ss, off);
    }
    float mu   = s * (1.f/DD);
    float var  = ss * (1.f/DD) - mu*mu;
    float rstd = rsqrtf(var + 1e-5f);
    float4 gm0 = ld4(gamma + lane*4),     gm1 = ld4(gamma + 128 + lane*4);
    float4 bt0 = ld4(beta  + lane*4),     bt1 = ld4(beta  + 128 + lane*4);
    float4 y0, y1;
    y0.x = (x0.x-mu)*rstd*gm0.x + bt0.x;  y0.y = (x0.y-mu)*rstd*gm0.y + bt0.y;
    y0.z = (x0.z-mu)*rstd*gm0.z + bt0.z;  y0.w = (x0.w-mu)*rstd*gm0.w + bt0.w;
    y1.x = (x1.x-mu)*rstd*gm1.x + bt1.x;  y1.y = (x1.y-mu)*rstd*gm1.y + bt1.y;
    y1.z = (x1.z-mu)*rstd*gm1.z + bt1.z;  y1.w = (x1.w-mu)*rstd*gm1.w + bt1.w;
    float* out = g_qn + (size_t)gw*DD;
    *(float4*)(out + lane*4)       = y0;
    *(float4*)(out + 128 + lane*4) = y1;
    // qbk = qn . u + c0
    float4 u0 = ld4(g_u + lane*4), u1 = ld4(g_u + 128 + lane*4);
    float p = y0.x*u0.x + y0.y*u0.y + y0.z*u0.z + y0.w*u0.w
            + y1.x*u1.x + y1.y*u1.y + y1.z*u1.z + y1.w*u1.w;
#pragma unroll
    for (int off = 16; off; off >>= 1) p += __shfl_xor_sync(0xffffffffu, p, off);
    if (lane == 0) g_qbk[gw] = p + g_c0;
}

// ---------------- fp32 GEMM, K=256, N=256, packed f32x2 FMA ----------------
// C[M,256] = A[M,256(lda)] @ B[256,256]  (+ mode-specific epilogue)
// mode 0: A=pA(Wq)          B=g_WkT  C=g_M
// mode 1: A=pA(Wkv+256,512) B=pB(Wo) C=g_W2
// mode 2: A=g_qn            B=g_M    C=g_qt    (+ g_v1 bias)
// mode 3: A=g_sbar          B=g_W2   C=pC(out) (+ resid + asum*wb2 + bo)
#define BM 64
#define BN 128
#define BK 16
__global__ __launch_bounds__(256) void k_gemm(int mode,
        const float* __restrict__ pA, int lda,
        const float* __restrict__ pB,
        float* __restrict__ pC,
        const float* __restrict__ pBias,
        const float* __restrict__ pResid)
{
    const float* A; const float* B; float* C;
    if      (mode == 0) { A = pA;     B = g_WkT; C = g_M;  }
    else if (mode == 1) { A = pA;     B = pB;    C = g_W2; }
    else if (mode == 2) { A = g_qn;   B = g_M;   C = g_qt; }
    else                { A = g_sbar; B = g_W2;  C = pC;   }

    __shared__ __align__(16) float As[BK][68];
    __shared__ __align__(16) float Bs[BK][132];

    int tid = threadIdx.x;
    int tx = tid & 15, ty = tid >> 4;
    int m0 = blockIdx.y * BM, n0 = blockIdx.x * BN;

    int arow = tid >> 2;            // 0..63
    int akq  = (tid & 3) * 4;       // 0,4,8,12
    int brow = tid >> 4;            // 0..15
    int bcol = (tid & 15) * 4;      // 0..60

    u64 acc[4][4];
#pragma unroll
    for (int i = 0; i < 4; i++)
#pragma unroll
        for (int j = 0; j < 4; j++) acc[i][j] = 0ull;

    for (int kt = 0; kt < DD; kt += BK) {
        float4 av  = ld4(A + (size_t)(m0+arow)*lda + kt + akq);
        float4 bv0 = ld4(B + (size_t)(kt+brow)*DD + n0 + bcol);
        float4 bv1 = ld4(B + (size_t)(kt+brow)*DD + n0 + 64 + bcol);
        __syncthreads();
        As[akq+0][arow] = av.x; As[akq+1][arow] = av.y;
        As[akq+2][arow] = av.z; As[akq+3][arow] = av.w;
        *(float4*)&Bs[brow][bcol]      = bv0;
        *(float4*)&Bs[brow][64 + bcol] = bv1;
        __syncthreads();
#pragma unroll
        for (int k = 0; k < BK; k++) {
            float4 a = *(const float4*)&As[k][ty*4];
            ulonglong2 bp0 = *(const ulonglong2*)&Bs[k][tx*8];
            ulonglong2 bp1 = *(const ulonglong2*)&Bs[k][tx*8 + 4];
            u64 ap;
            ap = pack2(a.x, a.x);
            FMA2(acc[0][0], ap, bp0.x); FMA2(acc[0][1], ap, bp0.y);
            FMA2(acc[0][2], ap, bp1.x); FMA2(acc[0][3], ap, bp1.y);
            ap = pack2(a.y, a.y);
            FMA2(acc[1][0], ap, bp0.x); FMA2(acc[1][1], ap, bp0.y);
            FMA2(acc[1][2], ap, bp1.x); FMA2(acc[1][3], ap, bp1.y);
            ap = pack2(a.z, a.z);
            FMA2(acc[2][0], ap, bp0.x); FMA2(acc[2][1], ap, bp0.y);
            FMA2(acc[2][2], ap, bp1.x); FMA2(acc[2][3], ap, bp1.y);
            ap = pack2(a.w, a.w);
            FMA2(acc[3][0], ap, bp0.x); FMA2(acc[3][1], ap, bp0.y);
            FMA2(acc[3][2], ap, bp1.x); FMA2(acc[3][3], ap, bp1.y);
        }
    }

#pragma unroll
    for (int i = 0; i < 4; i++) {
        int r = m0 + ty*4 + i;
        float asr = (mode == 3) ? g_asum[r] : 0.f;
#pragma unroll
        for (int j = 0; j < 4; j++) {
            int cidx = n0 + tx*8 + 2*j;
            float lo, hi;
            unpack2(acc[i][j], lo, hi);
            if (mode == 2) {
                lo += g_v1[cidx]; hi += g_v1[cidx+1];
            } else if (mode == 3) {
                lo += pResid[(size_t)r*DD + cidx]     + asr*g_wb2[cidx]   + pBias[cidx];
                hi += pResid[(size_t)r*DD + cidx + 1] + asr*g_wb2[cidx+1] + pBias[cidx+1];
            }
            *(float2*)&C[(size_t)r*DD + cidx] = make_float2(lo, hi);
        }
    }
}

// ---------------- fused bilinear gather + scores + softmax + weighted sum ----------------
__global__ __launch_bounds__(256) void k_attn(const float* __restrict__ feat,
                                              const float* __restrict__ coords,
                                              const int*   __restrict__ valid)
{
    int gw   = (blockIdx.x*256 + threadIdx.x) >> 5;
    int lane = threadIdx.x & 31;
    int b = gw >> 14;
    int n = gw & (DN - 1);

    const float* qtp = g_qt + (size_t)gw*DD;
    float4 qt0 = ld4(qtp + lane*4);
    float4 qt1 = ld4(qtp + 128 + lane*4);

    float4 a0[DC], a1[DC];
    float  sc[DC];

#pragma unroll
    for (int c = 0; c < DC; c++) {
        int ci = b*DC + c;
        float2 xy = *((const float2*)coords + (size_t)ci*DN + n);
        float x = (xy.x + 1.0f)*0.5f*(float)(DW - 1);
        float y = (xy.y + 1.0f)*0.5f*(float)(DH - 1);
        float x0f = floorf(x), y0f = floorf(y);
        float wx = x - x0f,    wy = y - y0f;
        int x0 = (int)x0f, y0 = (int)y0f;
        int x1 = x0 + 1,   y1 = y0 + 1;
        float w00 = (1.f-wy)*(1.f-wx), w01 = (1.f-wy)*wx;
        float w10 = wy*(1.f-wx),       w11 = wy*wx;
        bool bx0 = (unsigned)x0 < DW, bx1 = (unsigned)x1 < DW;
        bool by0 = (unsigned)y0 < DH, by1 = (unsigned)y1 < DH;
        w00 = (bx0 && by0) ? w00 : 0.f;  w01 = (bx1 && by0) ? w01 : 0.f;
        w10 = (bx0 && by1) ? w10 : 0.f;  w11 = (bx1 && by1) ? w11 : 0.f;
        int xc0 = min(max(x0,0),DW-1), xc1 = min(max(x1,0),DW-1);
        int yc0 = min(max(y0,0),DH-1), yc1 = min(max(y1,0),DH-1);

        const float* base = feat + (size_t)ci*(DH*DW*DD) + lane*4;
        const float* p00 = base + (yc0*DW + xc0)*DD;
        const float* p01 = base + (yc0*DW + xc1)*DD;
        const float* p10 = base + (yc1*DW + xc0)*DD;
        const float* p11 = base + (yc1*DW + xc1)*DD;
        float4 f00 = ld4(p00),     f01 = ld4(p01),     f10 = ld4(p10),     f11 = ld4(p11);
        float4 g00 = ld4(p00+128), g01 = ld4(p01+128), g10 = ld4(p10+128), g11 = ld4(p11+128);

        float4 va, vb;
        va.x = w00*f00.x + w01*f01.x + w10*f10.x + w11*f11.x;
        va.y = w00*f00.y + w01*f01.y + w10*f10.y + w11*f11.y;
        va.z = w00*f00.z + w01*f01.z + w10*f10.z + w11*f11.z;
        va.w = w00*f00.w + w01*f01.w + w10*f10.w + w11*f11.w;
        vb.x = w00*g00.x + w01*g01.x + w10*g10.x + w11*g11.x;
        vb.y = w00*g00.y + w01*g01.y + w10*g10.y + w11*g11.y;
        vb.z = w00*g00.z + w01*g01.z + w10*g10.z + w11*g11.z;
        vb.w = w00*g00.w + w01*g01.w + w10*g10.w + w11*g11.w;
        a0[c] = va; a1[c] = vb;
        sc[c] = va.x*qt0.x + va.y*qt0.y + va.z*qt0.z + va.w*qt0.w
              + vb.x*qt1.x + vb.y*qt1.y + vb.z*qt1.z + vb.w*qt1.w;
    }

#pragma unroll
    for (int c = 0; c < DC; c++)
#pragma unroll
        for (int off = 16; off; off >>= 1)
            sc[c] += __shfl_xor_sync(0xffffffffu, sc[c], off);

    float qb = g_qbk[gw];
    float m = -INFINITY;
#pragma unroll
    for (int c = 0; c < DC; c++) {
        int vm = valid[(size_t)(b*DC + c)*DN + n];
        sc[c] = vm ? (sc[c] + qb)*0.0625f : -INFINITY;
        m = fmaxf(m, sc[c]);
    }

    float4 s0 = make_float4(0.f,0.f,0.f,0.f), s1 = make_float4(0.f,0.f,0.f,0.f);
    float Asum = 0.f;
    if (m != -INFINITY) {
        float w[DC];
        float es = 0.f;
#pragma unroll
        for (int c = 0; c < DC; c++) { w[c] = expf(sc[c] - m); es += w[c]; }
        float r = 1.f/es;
#pragma unroll
        for (int c = 0; c < DC; c++) {
            float at = w[c]*r;
            Asum += at;
            s0.x += at*a0[c].x; s0.y += at*a0[c].y; s0.z += at*a0[c].z; s0.w += at*a0[c].w;
            s1.x += at*a1[c].x; s1.y += at*a1[c].y; s1.z += at*a1[c].z; s1.w += at*a1[c].w;
        }
    }
    float* sp = g_sbar + (size_t)gw*DD;
    *(float4*)(sp + lane*4)       = s0;
    *(float4*)(sp + 128 + lane*4) = s1;
    if (lane == 0) g_asum[gw] = Asum;
}

// ---------------- launch ----------------
extern "C" void kernel_launch(void* const* d_in, const int* in_sizes, int n_in,
                              void* d_out, int out_size)
{
    const float* queries = (const float*)d_in[0];
    const float* feat    = (const float*)d_in[1];
    const float* coords  = (const float*)d_in[2];
    const int*   valid   = (const int*)  d_in[3];
    const float* Wq      = (const float*)d_in[4];
    const float* bq      = (const float*)d_in[5];
    const float* Wkv     = (const float*)d_in[6];
    const float* bkv     = (const float*)d_in[7];
    const float* Wo      = (const float*)d_in[8];
    const float* bo      = (const float*)d_in[9];
    const float* gamma   = (const float*)d_in[10];
    const float* beta    = (const float*)d_in[11];
    float* out = (float*)d_out;

    k_vec<<<1, 256>>>(Wq, bq, Wkv, bkv, Wo);
    k_tr <<<256, 256>>>(Wkv);
    // M = Wq @ Wk^T
    k_gemm<<<dim3(2,4), 256>>>(0, Wq, DD, nullptr, nullptr, nullptr, nullptr);
    // W2 = Wv @ Wo   (Wv = Wkv[:, D:], row stride 2D)
    k_gemm<<<dim3(2,4), 256>>>(1, Wkv + DD, 2*DD, Wo, nullptr, nullptr, nullptr);
    // layernorm + qbk
    k_ln<<<ROWS/8, 256>>>(queries, gamma, beta);
    // qt = qn @ M + v1
    k_gemm<<<dim3(2, ROWS/BM), 256>>>(2, nullptr, DD, nullptr, nullptr, nullptr, nullptr);
    // fused gather + attention
    k_attn<<<ROWS/8, 256>>>(feat, coords, valid);
    // out = residual + sbar @ W2 + asum*wb2 + bo
    k_gemm<<<dim3(2, ROWS/BM), 256>>>(3, nullptr, DD, nullptr, out, bo, queries);
}

// round 3
// speedup vs baseline: 1.5995x; 1.5995x over previous
#include <cuda_runtime.h>
#include <math.h>
#include <stdint.h>

#define DB 2
#define DC 8
#define DN 16384
#define DD 256
#define DH 64
#define DW 64
#define ROWS (DB*DN)

// ---------------- scratch ----------------
__device__ __align__(256) float g_qn_hi [ROWS*DD];
__device__ __align__(256) float g_qn_lo [ROWS*DD];
__device__ __align__(256) float g_qt    [ROWS*DD];
__device__ __align__(256) float g_sbar_hi[ROWS*DD];
__device__ __align__(256) float g_sbar_lo[ROWS*DD];
__device__ float g_qbk [ROWS];
__device__ float g_asum[ROWS];
__device__ __align__(256) float g_WqT [DD*DD];
__device__ __align__(256) float g_WoT [DD*DD];
__device__ __align__(256) float g_WvT [DD*DD];
__device__ __align__(256) float g_WkT [DD*DD];
__device__ __align__(256) float g_MT_hi [DD*DD];
__device__ __align__(256) float g_MT_lo [DD*DD];
__device__ __align__(256) float g_W2T_hi[DD*DD];
__device__ __align__(256) float g_W2T_lo[DD*DD];
__device__ float g_v1 [DD];
__device__ float g_u  [DD];
__device__ float g_wb2[DD];
__device__ float g_c0;

__device__ __forceinline__ float4 ld4(const float* p) { return *(const float4*)p; }

__device__ __forceinline__ void tf32_split(float x, float& hi, float& lo) {
    unsigned h, l;
    asm("cvt.rna.tf32.f32 %0, %1;" : "=r"(h) : "f"(x));
    float hf = __uint_as_float(h);
    float r = x - hf;
    asm("cvt.rna.tf32.f32 %0, %1;" : "=r"(l) : "f"(r));
    hi = hf; lo = __uint_as_float(l);
}

__device__ __forceinline__ uint32_t smem_u32(const void* p) {
    uint32_t a;
    asm("{ .reg .u64 t; cvta.to.shared.u64 t, %1; cvt.u32.u64 %0, t; }" : "=r"(a) : "l"(p));
    return a;
}

__device__ __forceinline__ void cpa16(uint32_t d, const float* s) {
    asm volatile("cp.async.cg.shared.global [%0], [%1], 16;" :: "r"(d), "l"(s));
}

// ---------------- transposes: WqT, WoT, WvT, WkT ----------------
__global__ void k_tr(const float* __restrict__ Wq, const float* __restrict__ Wo,
                     const float* __restrict__ Wkv)
{
    __shared__ float t[32][33];
    int z = blockIdx.z;
    const float* src; int ld, off; float* dst;
    if      (z == 0) { src = Wq;  ld = 256; off = 0;   dst = g_WqT; }
    else if (z == 1) { src = Wo;  ld = 256; off = 0;   dst = g_WoT; }
    else if (z == 2) { src = Wkv; ld = 512; off = 256; dst = g_WvT; }
    else             { src = Wkv; ld = 512; off = 0;   dst = g_WkT; }
    int bx = blockIdx.x*32, by = blockIdx.y*32;
    for (int yy = threadIdx.y; yy < 32; yy += 8)
        t[yy][threadIdx.x] = src[(size_t)(by+yy)*ld + off + bx + threadIdx.x];
    __syncthreads();
    for (int yy = threadIdx.y; yy < 32; yy += 8)
        dst[(size_t)(bx+yy)*256 + by + threadIdx.x] = t[threadIdx.x][yy];
}

// ---------------- small vectors ----------------
__global__ void k_vec(const float* __restrict__ bq, const float* __restrict__ bkv,
                      const float* __restrict__ Wo)
{
    int which = blockIdx.x, t = threadIdx.x;
    __shared__ float v[256];
    if      (which == 0) v[t] = bkv[t];
    else if (which == 1) v[t] = bq[t];
    else                 v[t] = bkv[256 + t];
    __syncthreads();
    float acc = 0.f;
    if (which == 0) {
        for (int d = 0; d < 256; d++) acc += g_WqT[d*256 + t] * v[d];
        g_u[t] = acc;
        if (t == 0) { float c = 0.f; for (int d = 0; d < 256; d++) c += bq[d]*bkv[d]; g_c0 = c; }
    } else if (which == 1) {
        for (int d = 0; d < 256; d++) acc += g_WkT[d*256 + t] * v[d];
        g_v1[t] = acc;
    } else {
        for (int f = 0; f < 256; f++) acc += Wo[f*256 + t] * v[f];
        g_wb2[t] = acc;
    }
}

// ---------------- MT[f][e] = Wk@Wq^T ; W2T[t][f] = (Wv@Wo)^T ----------------
__global__ __launch_bounds__(256) void k_pre(const float* __restrict__ Wkv)
{
    __shared__ float Ar[8][256];
    int r0 = blockIdx.x * 8;
    const float* Bsrc; float *Chi, *Clo;
    if (blockIdx.y == 0) {
        for (int i = threadIdx.x; i < 8*256; i += 256) {
            int j = i >> 8, d = i & 255;
            Ar[j][d] = Wkv[(size_t)(r0+j)*512 + d];            // Wk rows
        }
        Bsrc = g_WqT; Chi = g_MT_hi; Clo = g_MT_lo;
    } else {
        for (int i = threadIdx.x; i < 8*256; i += 256) {
            int j = i >> 8, d = i & 255;
            Ar[j][d] = g_WoT[(size_t)(r0+j)*256 + d];          // WoT rows
        }
        Bsrc = g_WvT; Chi = g_W2T_hi; Clo = g_W2T_lo;
    }
    __syncthreads();
    int e = threadIdx.x;
    float acc[8];
#pragma unroll
    for (int j = 0; j < 8; j++) acc[j] = 0.f;
    for (int d = 0; d < 256; d++) {
        float b = Bsrc[(size_t)d*256 + e];
#pragma unroll
        for (int j = 0; j < 8; j++) acc[j] += Ar[j][d] * b;
    }
#pragma unroll
    for (int j = 0; j < 8; j++) {
        float hi, lo; tf32_split(acc[j], hi, lo);
        Chi[(size_t)(r0+j)*256 + e] = hi;
        Clo[(size_t)(r0+j)*256 + e] = lo;
    }
}

// ---------------- layernorm + qbk, emits tf32 hi/lo ----------------
__global__ __launch_bounds__(256) void k_ln(const float* __restrict__ q,
                                            const float* __restrict__ gamma,
                                            const float* __restrict__ beta)
{
    int gw   = (blockIdx.x*256 + threadIdx.x) >> 5;
    int lane = threadIdx.x & 31;
    const float* row = q + (size_t)gw*DD;
    float4 x0 = ld4(row + lane*4);
    float4 x1 = ld4(row + 128 + lane*4);
    float s  = x0.x+x0.y+x0.z+x0.w + x1.x+x1.y+x1.z+x1.w;
    float ss = x0.x*x0.x+x0.y*x0.y+x0.z*x0.z+x0.w*x0.w
             + x1.x*x1.x+x1.y*x1.y+x1.z*x1.z+x1.w*x1.w;
#pragma unroll
    for (int off = 16; off; off >>= 1) {
        s  += __shfl_xor_sync(0xffffffffu, s,  off);
        ss += __shfl_xor_sync(0xffffffffu, ss, off);
    }
    float mu   = s * (1.f/DD);
    float var  = ss * (1.f/DD) - mu*mu;
    float rstd = rsqrtf(var + 1e-5f);
    float4 gm0 = ld4(gamma + lane*4), gm1 = ld4(gamma + 128 + lane*4);
    float4 bt0 = ld4(beta  + lane*4), bt1 = ld4(beta  + 128 + lane*4);
    float y[8];
    y[0] = (x0.x-mu)*rstd*gm0.x + bt0.x;  y[1] = (x0.y-mu)*rstd*gm0.y + bt0.y;
    y[2] = (x0.z-mu)*rstd*gm0.z + bt0.z;  y[3] = (x0.w-mu)*rstd*gm0.w + bt0.w;
    y[4] = (x1.x-mu)*rstd*gm1.x + bt1.x;  y[5] = (x1.y-mu)*rstd*gm1.y + bt1.y;
    y[6] = (x1.z-mu)*rstd*gm1.z + bt1.z;  y[7] = (x1.w-mu)*rstd*gm1.w + bt1.w;

    float hi[8], lo[8];
#pragma unroll
    for (int i = 0; i < 8; i++) tf32_split(y[i], hi[i], lo[i]);
    float* oh = g_qn_hi + (size_t)gw*DD;
    float* ol = g_qn_lo + (size_t)gw*DD;
    *(float4*)(oh + lane*4)       = make_float4(hi[0],hi[1],hi[2],hi[3]);
    *(float4*)(oh + 128 + lane*4) = make_float4(hi[4],hi[5],hi[6],hi[7]);
    *(float4*)(ol + lane*4)       = make_float4(lo[0],lo[1],lo[2],lo[3]);
    *(float4*)(ol + 128 + lane*4) = make_float4(lo[4],lo[5],lo[6],lo[7]);

    float4 u0 = ld4(g_u + lane*4), u1 = ld4(g_u + 128 + lane*4);
    float p = y[0]*u0.x + y[1]*u0.y + y[2]*u0.z + y[3]*u0.w
            + y[4]*u1.x + y[5]*u1.y + y[6]*u1.z + y[7]*u1.w;
#pragma unroll
    for (int off = 16; off; off >>= 1) p += __shfl_xor_sync(0xffffffffu, p, off);
    if (lane == 0) g_qbk[gw] = p + g_c0;
}

// ================= 3xTF32 mma.sync GEMM =================
// C[32768,256] = (Ahi+Alo)[M,K=256] @ (Bhi+Blo)^T, B stored [N=256][K=256] K-major.
// CTA: 128x128 tile, 8 warps (4x2), warp tile 32x64. K chunks of 16, double buffered.
#define MMA_OP(d, a, b) \
    asm volatile("mma.sync.aligned.m16n8k8.row.col.f32.tf32.tf32.f32 " \
        "{%0,%1,%2,%3}, {%4,%5,%6,%7}, {%8,%9}, {%0,%1,%2,%3};" \
        : "+f"(d[0]), "+f"(d[1]), "+f"(d[2]), "+f"(d[3]) \
        : "r"(a[0]), "r"(a[1]), "r"(a[2]), "r"(a[3]), "r"(b[0]), "r"(b[1]))

#define NSTG 16
#define STG_BYTES 40960
#define SMEM_MMA (2*STG_BYTES)

__global__ __launch_bounds__(256, 1) void k_mma(int mode, float* __restrict__ outp,
                                                const float* __restrict__ resid,
                                                const float* __restrict__ bo)
{
    const float *Ahi, *Alo, *Bhi, *Blo; float* C;
    if (mode == 2) { Ahi = g_qn_hi;   Alo = g_qn_lo;   Bhi = g_MT_hi;  Blo = g_MT_lo;  C = g_qt; }
    else           { Ahi = g_sbar_hi; Alo = g_sbar_lo; Bhi = g_W2T_hi; Blo = g_W2T_lo; C = outp; }

    extern __shared__ __align__(16) float smem[];
    uint32_t sb = smem_u32(smem);
    int tid = threadIdx.x, lane = tid & 31, wid = tid >> 5;
    int wm = wid >> 1, wn = wid & 1;
    int qr = lane >> 2, qc = lane & 3;
    size_t m0 = (size_t)blockIdx.y * 128;
    int n0 = blockIdx.x * 128;

    float acc[2][8][4];
#pragma unroll
    for (int mi = 0; mi < 2; mi++)
#pragma unroll
        for (int ni = 0; ni < 8; ni++)
#pragma unroll
            for (int t = 0; t < 4; t++) acc[mi][ni][t] = 0.f;

    // stage loader: 128 rows x 16 floats per tile (Ah, Al, Bh, Bl), row stride 20 floats
    {
        int kb = 0;
        for (int i = tid; i < 512; i += 256) {
            int row = i >> 2, seg = i & 3;
            uint32_t off = row*80 + seg*16;
            cpa16(sb + off,         Ahi + (m0 + row)*256 + kb + seg*4);
            cpa16(sb + 10240 + off, Alo + (m0 + row)*256 + kb + seg*4);
            cpa16(sb + 20480 + off, Bhi + (size_t)(n0 + row)*256 + kb + seg*4);
            cpa16(sb + 30720 + off, Blo + (size_t)(n0 + row)*256 + kb + seg*4);
        }
        asm volatile("cp.async.commit_group;");
    }

    for (int s = 0; s < NSTG; s++) {
        if (s + 1 < NSTG) {
            int kb = (s + 1) * 16;
            uint32_t base = sb + ((s + 1) & 1) * STG_BYTES;
            for (int i = tid; i < 512; i += 256) {
                int row = i >> 2, seg = i & 3;
                uint32_t off = row*80 + seg*16;
                cpa16(base + off,         Ahi + (m0 + row)*256 + kb + seg*4);
                cpa16(base + 10240 + off, Alo + (m0 + row)*256 + kb + seg*4);
                cpa16(base + 20480 + off, Bhi + (size_t)(n0 + row)*256 + kb + seg*4);
                cpa16(base + 30720 + off, Blo + (size_t)(n0 + row)*256 + kb + seg*4);
            }
            asm volatile("cp.async.commit_group;");
            asm volatile("cp.async.wait_group 1;");
        } else {
            asm volatile("cp.async.wait_group 0;");
        }
        __syncthreads();

        const float* St = smem + (s & 1) * (STG_BYTES/4);
        const float* Ah = St;
        const float* Al = St + 2560;
        const float* Bh = St + 5120;
        const float* Bl = St + 7680;

#pragma unroll
        for (int kk = 0; kk < 2; kk++) {
            int k0 = kk * 8;
            unsigned ah[2][4], al[2][4], bh[8][2], bl[8][2];
#pragma unroll
            for (int mi = 0; mi < 2; mi++) {
                int mb = (wm*32 + mi*16 + qr)*20 + k0 + qc;
                ah[mi][0] = __float_as_uint(Ah[mb]);
                ah[mi][1] = __float_as_uint(Ah[mb + 160]);
                ah[mi][2] = __float_as_uint(Ah[mb + 4]);
                ah[mi][3] = __float_as_uint(Ah[mb + 164]);
                al[mi][0] = __float_as_uint(Al[mb]);
                al[mi][1] = __float_as_uint(Al[mb + 160]);
                al[mi][2] = __float_as_uint(Al[mb + 4]);
                al[mi][3] = __float_as_uint(Al[mb + 164]);
            }
#pragma unroll
            for (int ni = 0; ni < 8; ni++) {
                int nb = (wn*64 + ni*8 + qr)*20 + k0 + qc;
                bh[ni][0] = __float_as_uint(Bh[nb]);
                bh[ni][1] = __float_as_uint(Bh[nb + 4]);
                bl[ni][0] = __float_as_uint(Bl[nb]);
                bl[ni][1] = __float_as_uint(Bl[nb + 4]);
            }
#pragma unroll
            for (int mi = 0; mi < 2; mi++)
#pragma unroll
                for (int ni = 0; ni < 8; ni++) {
                    MMA_OP(acc[mi][ni], ah[mi], bh[ni]);
                    MMA_OP(acc[mi][ni], ah[mi], bl[ni]);
                    MMA_OP(acc[mi][ni], al[mi], bh[ni]);
                }
        }
        __syncthreads();
    }

    // epilogue
#pragma unroll
    for (int mi = 0; mi < 2; mi++) {
        size_t r0 = m0 + wm*32 + mi*16 + qr;
        size_t r1 = r0 + 8;
        float as0 = 0.f, as1 = 0.f;
        if (mode == 3) { as0 = g_asum[r0]; as1 = g_asum[r1]; }
#pragma unroll
        for (int ni = 0; ni < 8; ni++) {
            int c = n0 + wn*64 + ni*8 + qc*2;
            float2 v0 = make_float2(acc[mi][ni][0], acc[mi][ni][1]);
            float2 v1 = make_float2(acc[mi][ni][2], acc[mi][ni][3]);
            if (mode == 2) {
                v0.x += g_v1[c]; v0.y += g_v1[c+1];
                v1.x += g_v1[c]; v1.y += g_v1[c+1];
            } else {
                float2 rs0 = *(const float2*)&resid[r0*256 + c];
                float2 rs1 = *(const float2*)&resid[r1*256 + c];
                float w0 = g_wb2[c], w1 = g_wb2[c+1];
                float b0 = bo[c], b1 = bo[c+1];
                v0.x += rs0.x + as0*w0 + b0;  v0.y += rs0.y + as0*w1 + b1;
                v1.x += rs1.x + as1*w0 + b0;  v1.y += rs1.y + as1*w1 + b1;
            }
            *(float2*)&C[r0*256 + c] = v0;
            *(float2*)&C[r1*256 + c] = v1;
        }
    }
}

// ---------------- fused bilinear gather + scores + softmax + weighted sum ----------------
__global__ __launch_bounds__(256) void k_attn(const float* __restrict__ feat,
                                              const float* __restrict__ coords,
                                              const int*   __restrict__ valid)
{
    int gw   = (blockIdx.x*256 + threadIdx.x) >> 5;
    int lane = threadIdx.x & 31;
    int b = gw >> 14;
    int n = gw & (DN - 1);

    const float* qtp = g_qt + (size_t)gw*DD;
    float4 qt0 = ld4(qtp + lane*4);
    float4 qt1 = ld4(qtp + 128 + lane*4);

    float4 a0[DC], a1[DC];
    float  sc[DC];

#pragma unroll
    for (int c = 0; c < DC; c++) {
        int ci = b*DC + c;
        float2 xy = *((const float2*)coords + (size_t)ci*DN + n);
        float x = (xy.x + 1.0f)*0.5f*(float)(DW - 1);
        float y = (xy.y + 1.0f)*0.5f*(float)(DH - 1);
        float x0f = floorf(x), y0f = floorf(y);
        float wx = x - x0f,    wy = y - y0f;
        int x0 = (int)x0f, y0 = (int)y0f;
        int x1 = x0 + 1,   y1 = y0 + 1;
        float w00 = (1.f-wy)*(1.f-wx), w01 = (1.f-wy)*wx;
        float w10 = wy*(1.f-wx),       w11 = wy*wx;
        bool bx0 = (unsigned)x0 < DW, bx1 = (unsigned)x1 < DW;
        bool by0 = (unsigned)y0 < DH, by1 = (unsigned)y1 < DH;
        w00 = (bx0 && by0) ? w00 : 0.f;  w01 = (bx1 && by0) ? w01 : 0.f;
        w10 = (bx0 && by1) ? w10 : 0.f;  w11 = (bx1 && by1) ? w11 : 0.f;
        int xc0 = min(max(x0,0),DW-1), xc1 = min(max(x1,0),DW-1);
        int yc0 = min(max(y0,0),DH-1), yc1 = min(max(y1,0),DH-1);

        const float* base = feat + (size_t)ci*(DH*DW*DD) + lane*4;
        const float* p00 = base + (yc0*DW + xc0)*DD;
        const float* p01 = base + (yc0*DW + xc1)*DD;
        const float* p10 = base + (yc1*DW + xc0)*DD;
        const float* p11 = base + (yc1*DW + xc1)*DD;
        float4 f00 = ld4(p00),     f01 = ld4(p01),     f10 = ld4(p10),     f11 = ld4(p11);
        float4 g00 = ld4(p00+128), g01 = ld4(p01+128), g10 = ld4(p10+128), g11 = ld4(p11+128);

        float4 va, vb;
        va.x = w00*f00.x + w01*f01.x + w10*f10.x + w11*f11.x;
        va.y = w00*f00.y + w01*f01.y + w10*f10.y + w11*f11.y;
        va.z = w00*f00.z + w01*f01.z + w10*f10.z + w11*f11.z;
        va.w = w00*f00.w + w01*f01.w + w10*f10.w + w11*f11.w;
        vb.x = w00*g00.x + w01*g01.x + w10*g10.x + w11*g11.x;
        vb.y = w00*g00.y + w01*g01.y + w10*g10.y + w11*g11.y;
        vb.z = w00*g00.z + w01*g01.z + w10*g10.z + w11*g11.z;
        vb.w = w00*g00.w + w01*g01.w + w10*g10.w + w11*g11.w;
        a0[c] = va; a1[c] = vb;
        sc[c] = va.x*qt0.x + va.y*qt0.y + va.z*qt0.z + va.w*qt0.w
              + vb.x*qt1.x + vb.y*qt1.y + vb.z*qt1.z + vb.w*qt1.w;
    }

#pragma unroll
    for (int c = 0; c < DC; c++)
#pragma unroll
        for (int off = 16; off; off >>= 1)
            sc[c] += __shfl_xor_sync(0xffffffffu, sc[c], off);

    float qb = g_qbk[gw];
    float m = -INFINITY;
#pragma unroll
    for (int c = 0; c < DC; c++) {
        int vm = valid[(size_t)(b*DC + c)*DN + n];
        sc[c] = vm ? (sc[c] + qb)*0.0625f : -INFINITY;
        m = fmaxf(m, sc[c]);
    }

    float4 s0 = make_float4(0.f,0.f,0.f,0.f), s1 = make_float4(0.f,0.f,0.f,0.f);
    float Asum = 0.f;
    if (m != -INFINITY) {
        float w[DC];
        float es = 0.f;
#pragma unroll
        for (int c = 0; c < DC; c++) { w[c] = expf(sc[c] - m); es += w[c]; }
        float r = 1.f/es;
#pragma unroll
        for (int c = 0; c < DC; c++) {
            float at = w[c]*r;
            Asum += at;
            s0.x += at*a0[c].x; s0.y += at*a0[c].y; s0.z += at*a0[c].z; s0.w += at*a0[c].w;
            s1.x += at*a1[c].x; s1.y += at*a1[c].y; s1.z += at*a1[c].z; s1.w += at*a1[c].w;
        }
    }
    float v[8] = {s0.x,s0.y,s0.z,s0.w,s1.x,s1.y,s1.z,s1.w};
    float hi[8], lo[8];
#pragma unroll
    for (int i = 0; i < 8; i++) tf32_split(v[i], hi[i], lo[i]);
    float* sh = g_sbar_hi + (size_t)gw*DD;
    float* sl = g_sbar_lo + (size_t)gw*DD;
    *(float4*)(sh + lane*4)       = make_float4(hi[0],hi[1],hi[2],hi[3]);
    *(float4*)(sh + 128 + lane*4) = make_float4(hi[4],hi[5],hi[6],hi[7]);
    *(float4*)(sl + lane*4)       = make_float4(lo[0],lo[1],lo[2],lo[3]);
    *(float4*)(sl + 128 + lane*4) = make_float4(lo[4],lo[5],lo[6],lo[7]);
    if (lane == 0) g_asum[gw] = Asum;
}

// ---------------- launch ----------------
extern "C" void kernel_launch(void* const* d_in, const int* in_sizes, int n_in,
                              void* d_out, int out_size)
{
    const float* queries = (const float*)d_in[0];
    const float* feat    = (const float*)d_in[1];
    const float* coords  = (const float*)d_in[2];
    const int*   valid   = (const int*)  d_in[3];
    const float* Wq      = (const float*)d_in[4];
    const float* bq      = (const float*)d_in[5];
    const float* Wkv     = (const float*)d_in[6];
    const float* bkv     = (const float*)d_in[7];
    const float* Wo      = (const float*)d_in[8];
    const float* bo      = (const float*)d_in[9];
    const float* gamma   = (const float*)d_in[10];
    const float* beta    = (const float*)d_in[11];
    float* out = (float*)d_out;

    cudaFuncSetAttribute(k_mma, cudaFuncAttributeMaxDynamicSharedMemorySize, SMEM_MMA);

    k_tr <<<dim3(8,8,4), dim3(32,8)>>>(Wq, Wo, Wkv);
    k_vec<<<3, 256>>>(bq, bkv, Wo);
    k_pre<<<dim3(32,2), 256>>>(Wkv);
    k_ln <<<ROWS/8, 256>>>(queries, gamma, beta);
    k_mma<<<dim3(2, ROWS/128), 256, SMEM_MMA>>>(2, nullptr, nullptr, nullptr);
    k_attn<<<ROWS/8, 256>>>(feat, coords, valid);
    k_mma<<<dim3(2, ROWS/128), 256, SMEM_MMA>>>(3, out, queries, bo);
}

// round 4
// speedup vs baseline: 1.6468x; 1.0295x over previous
#include <cuda_runtime.h>
#include <math.h>
#include <stdint.h>

#define DB 2
#define DC 8
#define DN 16384
#define DD 256
#define DH 64
#define DW 64
#define ROWS (DB*DN)

// ---------------- scratch ----------------
__device__ __align__(256) float g_qn  [ROWS*DD];
__device__ __align__(256) float g_qt  [ROWS*DD];
__device__ __align__(256) float g_sbar[ROWS*DD];
__device__ float g_qbk [ROWS];
__device__ float g_asum[ROWS];
__device__ __align__(256) float g_WqT [DD*DD];
__device__ __align__(256) float g_WoT [DD*DD];
__device__ __align__(256) float g_WvT [DD*DD];
__device__ __align__(256) float g_WkT [DD*DD];
__device__ __align__(256) float g_MT_hi [DD*DD];
__device__ __align__(256) float g_MT_lo [DD*DD];
__device__ __align__(256) float g_W2T_hi[DD*DD];
__device__ __align__(256) float g_W2T_lo[DD*DD];
__device__ float g_v1 [DD];
__device__ float g_u  [DD];
__device__ float g_wb2[DD];
__device__ float g_c0;

__device__ __forceinline__ float4 ld4(const float* p) { return *(const float4*)p; }

__device__ __forceinline__ void tf32_split(float x, float& hi, float& lo) {
    unsigned h, l;
    asm("cvt.rna.tf32.f32 %0, %1;" : "=r"(h) : "f"(x));
    float hf = __uint_as_float(h);
    float r = x - hf;
    asm("cvt.rna.tf32.f32 %0, %1;" : "=r"(l) : "f"(r));
    hi = hf; lo = __uint_as_float(l);
}
__device__ __forceinline__ void tf32_split_u(float x, unsigned& hi, unsigned& lo) {
    asm("cvt.rna.tf32.f32 %0, %1;" : "=r"(hi) : "f"(x));
    float r = x - __uint_as_float(hi);
    asm("cvt.rna.tf32.f32 %0, %1;" : "=r"(lo) : "f"(r));
}

__device__ __forceinline__ uint32_t smem_u32(const void* p) {
    uint32_t a;
    asm("{ .reg .u64 t; cvta.to.shared.u64 t, %1; cvt.u32.u64 %0, t; }" : "=r"(a) : "l"(p));
    return a;
}

__device__ __forceinline__ void cpa16(uint32_t d, const float* s) {
    asm volatile("cp.async.cg.shared.global [%0], [%1], 16;" :: "r"(d), "l"(s));
}

// ---------------- transposes: WqT, WoT, WvT, WkT ----------------
__global__ void k_tr(const float* __restrict__ Wq, const float* __restrict__ Wo,
                     const float* __restrict__ Wkv)
{
    __shared__ float t[32][33];
    int z = blockIdx.z;
    const float* src; int ld, off; float* dst;
    if      (z == 0) { src = Wq;  ld = 256; off = 0;   dst = g_WqT; }
    else if (z == 1) { src = Wo;  ld = 256; off = 0;   dst = g_WoT; }
    else if (z == 2) { src = Wkv; ld = 512; off = 256; dst = g_WvT; }
    else             { src = Wkv; ld = 512; off = 0;   dst = g_WkT; }
    int bx = blockIdx.x*32, by = blockIdx.y*32;
    for (int yy = threadIdx.y; yy < 32; yy += 8)
        t[yy][threadIdx.x] = src[(size_t)(by+yy)*ld + off + bx + threadIdx.x];
    __syncthreads();
    for (int yy = threadIdx.y; yy < 32; yy += 8)
        dst[(size_t)(bx+yy)*256 + by + threadIdx.x] = t[threadIdx.x][yy];
}

// ---------------- small vectors ----------------
__global__ void k_vec(const float* __restrict__ bq, const float* __restrict__ bkv,
                      const float* __restrict__ Wo)
{
    int which = blockIdx.x, t = threadIdx.x;
    __shared__ float v[256];
    if      (which == 0) v[t] = bkv[t];
    else if (which == 1) v[t] = bq[t];
    else                 v[t] = bkv[256 + t];
    __syncthreads();
    float acc = 0.f;
    if (which == 0) {
        for (int d = 0; d < 256; d++) acc += g_WqT[d*256 + t] * v[d];
        g_u[t] = acc;
        if (t == 0) { float c = 0.f; for (int d = 0; d < 256; d++) c += bq[d]*bkv[d]; g_c0 = c; }
    } else if (which == 1) {
        for (int d = 0; d < 256; d++) acc += g_WkT[d*256 + t] * v[d];
        g_v1[t] = acc;
    } else {
        for (int f = 0; f < 256; f++) acc += Wo[f*256 + t] * v[f];
        g_wb2[t] = acc;
    }
}

// ---------------- MT[f][e] = Wk@Wq^T ; W2T[t][f] = (Wv@Wo)^T ----------------
__global__ __launch_bounds__(256) void k_pre(const float* __restrict__ Wkv)
{
    __shared__ float Ar[8][256];
    int r0 = blockIdx.x * 8;
    const float* Bsrc; float *Chi, *Clo;
    if (blockIdx.y == 0) {
        for (int i = threadIdx.x; i < 8*256; i += 256) {
            int j = i >> 8, d = i & 255;
            Ar[j][d] = Wkv[(size_t)(r0+j)*512 + d];            // Wk rows
        }
        Bsrc = g_WqT; Chi = g_MT_hi; Clo = g_MT_lo;
    } else {
        for (int i = threadIdx.x; i < 8*256; i += 256) {
            int j = i >> 8, d = i & 255;
            Ar[j][d] = g_WoT[(size_t)(r0+j)*256 + d];          // WoT rows
        }
        Bsrc = g_WvT; Chi = g_W2T_hi; Clo = g_W2T_lo;
    }
    __syncthreads();
    int e = threadIdx.x;
    float acc[8];
#pragma unroll
    for (int j = 0; j < 8; j++) acc[j] = 0.f;
    for (int d = 0; d < 256; d++) {
        float b = Bsrc[(size_t)d*256 + e];
#pragma unroll
        for (int j = 0; j < 8; j++) acc[j] += Ar[j][d] * b;
    }
#pragma unroll
    for (int j = 0; j < 8; j++) {
        float hi, lo; tf32_split(acc[j], hi, lo);
        Chi[(size_t)(r0+j)*256 + e] = hi;
        Clo[(size_t)(r0+j)*256 + e] = lo;
    }
}

// ---------------- layernorm + qbk ----------------
__global__ __launch_bounds__(256) void k_ln(const float* __restrict__ q,
                                            const float* __restrict__ gamma,
                                            const float* __restrict__ beta)
{
    int gw   = (blockIdx.x*256 + threadIdx.x) >> 5;
    int lane = threadIdx.x & 31;
    const float* row = q + (size_t)gw*DD;
    float4 x0 = ld4(row + lane*4);
    float4 x1 = ld4(row + 128 + lane*4);
    float s  = x0.x+x0.y+x0.z+x0.w + x1.x+x1.y+x1.z+x1.w;
    float ss = x0.x*x0.x+x0.y*x0.y+x0.z*x0.z+x0.w*x0.w
             + x1.x*x1.x+x1.y*x1.y+x1.z*x1.z+x1.w*x1.w;
#pragma unroll
    for (int off = 16; off; off >>= 1) {
        s  += __shfl_xor_sync(0xffffffffu, s,  off);
        ss += __shfl_xor_sync(0xffffffffu, ss, off);
    }
    float mu   = s * (1.f/DD);
    float var  = ss * (1.f/DD) - mu*mu;
    float rstd = rsqrtf(var + 1e-5f);
    float4 gm0 = ld4(gamma + lane*4), gm1 = ld4(gamma + 128 + lane*4);
    float4 bt0 = ld4(beta  + lane*4), bt1 = ld4(beta  + 128 + lane*4);
    float4 y0, y1;
    y0.x = (x0.x-mu)*rstd*gm0.x + bt0.x;  y0.y = (x0.y-mu)*rstd*gm0.y + bt0.y;
    y0.z = (x0.z-mu)*rstd*gm0.z + bt0.z;  y0.w = (x0.w-mu)*rstd*gm0.w + bt0.w;
    y1.x = (x1.x-mu)*rstd*gm1.x + bt1.x;  y1.y = (x1.y-mu)*rstd*gm1.y + bt1.y;
    y1.z = (x1.z-mu)*rstd*gm1.z + bt1.z;  y1.w = (x1.w-mu)*rstd*gm1.w + bt1.w;
    float* o = g_qn + (size_t)gw*DD;
    *(float4*)(o + lane*4)       = y0;
    *(float4*)(o + 128 + lane*4) = y1;

    float4 u0 = ld4(g_u + lane*4), u1 = ld4(g_u + 128 + lane*4);
    float p = y0.x*u0.x + y0.y*u0.y + y0.z*u0.z + y0.w*u0.w
            + y1.x*u1.x + y1.y*u1.y + y1.z*u1.z + y1.w*u1.w;
#pragma unroll
    for (int off = 16; off; off >>= 1) p += __shfl_xor_sync(0xffffffffu, p, off);
    if (lane == 0) g_qbk[gw] = p + g_c0;
}

// ================= 3xTF32 mma.sync GEMM, A split on the fly =================
// C[32768,256] = A[M,K=256] @ (Bhi+Blo)^T, B stored [N=256][K=256] K-major.
// CTA: 128x128, 8 warps (4x2), warp tile 32x64. K chunks of 16, 3-stage cp.async.
#define MMA_OP(d, a, b) \
    asm volatile("mma.sync.aligned.m16n8k8.row.col.f32.tf32.tf32.f32 " \
        "{%0,%1,%2,%3}, {%4,%5,%6,%7}, {%8,%9}, {%0,%1,%2,%3};" \
        : "+f"(d[0]), "+f"(d[1]), "+f"(d[2]), "+f"(d[3]) \
        : "r"(a[0]), "r"(a[1]), "r"(a[2]), "r"(a[3]), "r"(b[0]), "r"(b[1]))

#define NSTG 16
#define STG_FLOATS 7680
#define STG_BYTES  30720
#define SMEM_MMA   (3*STG_BYTES)

__device__ __forceinline__ void ld_stage(uint32_t base,
        const float* __restrict__ Afp, const float* __restrict__ Bhi,
        const float* __restrict__ Blo, size_t m0, int n0, int kb, int tid)
{
    for (int i = tid; i < 512; i += 256) {
        int row = i >> 2, seg = i & 3;
        uint32_t off = row*80 + seg*16;
        cpa16(base + off,         Afp + (m0 + row)*256 + kb + seg*4);
        cpa16(base + 10240 + off, Bhi + (size_t)(n0 + row)*256 + kb + seg*4);
        cpa16(base + 20480 + off, Blo + (size_t)(n0 + row)*256 + kb + seg*4);
    }
    asm volatile("cp.async.commit_group;");
}

__global__ __launch_bounds__(256, 1) void k_mma(int mode, float* __restrict__ outp,
                                                const float* __restrict__ resid,
                                                const float* __restrict__ bo)
{
    const float *Afp, *Bhi, *Blo; float* C;
    if (mode == 2) { Afp = g_qn;   Bhi = g_MT_hi;  Blo = g_MT_lo;  C = g_qt; }
    else           { Afp = g_sbar; Bhi = g_W2T_hi; Blo = g_W2T_lo; C = outp; }

    extern __shared__ __align__(16) float smem[];
    uint32_t sb = smem_u32(smem);
    int tid = threadIdx.x, lane = tid & 31, wid = tid >> 5;
    int wm = wid >> 1, wn = wid & 1;
    int qr = lane >> 2, qc = lane & 3;
    size_t m0 = (size_t)blockIdx.y * 128;
    int n0 = blockIdx.x * 128;

    float acc[2][8][4];
#pragma unroll
    for (int mi = 0; mi < 2; mi++)
#pragma unroll
        for (int ni = 0; ni < 8; ni++)
#pragma unroll
            for (int t = 0; t < 4; t++) acc[mi][ni][t] = 0.f;

    ld_stage(sb,             Afp, Bhi, Blo, m0, n0, 0,  tid);
    ld_stage(sb + STG_BYTES, Afp, Bhi, Blo, m0, n0, 16, tid);

    for (int s = 0; s < NSTG; s++) {
        if (s == NSTG - 1) asm volatile("cp.async.wait_group 0;");
        else               asm volatile("cp.async.wait_group 1;");
        __syncthreads();
        if (s + 2 < NSTG)
            ld_stage(sb + ((s + 2) % 3)*STG_BYTES, Afp, Bhi, Blo, m0, n0, (s + 2)*16, tid);

        const float* St = smem + (s % 3) * STG_FLOATS;
        const float* Ah = St;
        const float* Bh = St + 2560;
        const float* Bl = St + 5120;

#pragma unroll
        for (int kk = 0; kk < 2; kk++) {
            int k0 = kk * 8;
            unsigned ah[2][4], al[2][4], bh[8][2], bl[8][2];
#pragma unroll
            for (int mi = 0; mi < 2; mi++) {
                int mb = (wm*32 + mi*16 + qr)*20 + k0 + qc;
                tf32_split_u(Ah[mb],       ah[mi][0], al[mi][0]);
                tf32_split_u(Ah[mb + 160], ah[mi][1], al[mi][1]);
                tf32_split_u(Ah[mb + 4],   ah[mi][2], al[mi][2]);
                tf32_split_u(Ah[mb + 164], ah[mi][3], al[mi][3]);
            }
#pragma unroll
            for (int ni = 0; ni < 8; ni++) {
                int nb = (wn*64 + ni*8 + qr)*20 + k0 + qc;
                bh[ni][0] = __float_as_uint(Bh[nb]);
                bh[ni][1] = __float_as_uint(Bh[nb + 4]);
                bl[ni][0] = __float_as_uint(Bl[nb]);
                bl[ni][1] = __float_as_uint(Bl[nb + 4]);
            }
#pragma unroll
            for (int mi = 0; mi < 2; mi++)
#pragma unroll
                for (int ni = 0; ni < 8; ni++) {
                    MMA_OP(acc[mi][ni], ah[mi], bh[ni]);
                    MMA_OP(acc[mi][ni], ah[mi], bl[ni]);
                    MMA_OP(acc[mi][ni], al[mi], bh[ni]);
                }
        }
    }

    // epilogue
#pragma unroll
    for (int mi = 0; mi < 2; mi++) {
        size_t r0 = m0 + wm*32 + mi*16 + qr;
        size_t r1 = r0 + 8;
        float as0 = 0.f, as1 = 0.f;
        if (mode == 3) { as0 = g_asum[r0]; as1 = g_asum[r1]; }
#pragma unroll
        for (int ni = 0; ni < 8; ni++) {
            int c = n0 + wn*64 + ni*8 + qc*2;
            float2 v0 = make_float2(acc[mi][ni][0], acc[mi][ni][1]);
            float2 v1 = make_float2(acc[mi][ni][2], acc[mi][ni][3]);
            if (mode == 2) {
                v0.x += g_v1[c]; v0.y += g_v1[c+1];
                v1.x += g_v1[c]; v1.y += g_v1[c+1];
            } else {
                float2 rs0 = *(const float2*)&resid[r0*256 + c];
                float2 rs1 = *(const float2*)&resid[r1*256 + c];
                float w0 = g_wb2[c], w1 = g_wb2[c+1];
                float b0 = bo[c], b1 = bo[c+1];
                v0.x += rs0.x + as0*w0 + b0;  v0.y += rs0.y + as0*w1 + b1;
                v1.x += rs1.x + as1*w0 + b0;  v1.y += rs1.y + as1*w1 + b1;
            }
            *(float2*)&C[r0*256 + c] = v0;
            *(float2*)&C[r1*256 + c] = v1;
        }
    }
}

// ---------------- fused bilinear gather + scores + softmax + weighted sum ----------------
__global__ __launch_bounds__(256) void k_attn(const float* __restrict__ feat,
                                              const float* __restrict__ coords,
                                              const int*   __restrict__ valid)
{
    int gw   = (blockIdx.x*256 + threadIdx.x) >> 5;
    int lane = threadIdx.x & 31;
    int b = gw >> 14;
    int n = gw & (DN - 1);

    const float* qtp = g_qt + (size_t)gw*DD;
    float4 qt0 = ld4(qtp + lane*4);
    float4 qt1 = ld4(qtp + 128 + lane*4);

    int vm[DC];
#pragma unroll
    for (int c = 0; c < DC; c++)
        vm[c] = valid[(size_t)(b*DC + c)*DN + n];

    float4 a0[DC], a1[DC];
    float  sc[DC];

#pragma unroll
    for (int c = 0; c < DC; c++) {
        sc[c] = -INFINITY;
        if (!vm[c]) continue;          // warp-uniform skip: one warp = one (b,n)
        int ci = b*DC + c;
        float2 xy = *((const float2*)coords + (size_t)ci*DN + n);
        float x = (xy.x + 1.0f)*0.5f*(float)(DW - 1);
        float y = (xy.y + 1.0f)*0.5f*(float)(DH - 1);
        float x0f = floorf(x), y0f = floorf(y);
        float wx = x - x0f,    wy = y - y0f;
        int x0 = (int)x0f, y0 = (int)y0f;
        int x1 = x0 + 1,   y1 = y0 + 1;
        float w00 = (1.f-wy)*(1.f-wx), w01 = (1.f-wy)*wx;
        float w10 = wy*(1.f-wx),       w11 = wy*wx;
        bool bx0 = (unsigned)x0 < DW, bx1 = (unsigned)x1 < DW;
        bool by0 = (unsigned)y0 < DH, by1 = (unsigned)y1 < DH;
        w00 = (bx0 && by0) ? w00 : 0.f;  w01 = (bx1 && by0) ? w01 : 0.f;
        w10 = (bx0 && by1) ? w10 : 0.f;  w11 = (bx1 && by1) ? w11 : 0.f;
        int xc0 = min(max(x0,0),DW-1), xc1 = min(max(x1,0),DW-1);
        int yc0 = min(max(y0,0),DH-1), yc1 = min(max(y1,0),DH-1);

        const float* base = feat + (size_t)ci*(DH*DW*DD) + lane*4;
        const float* p00 = base + (yc0*DW + xc0)*DD;
        const float* p01 = base + (yc0*DW + xc1)*DD;
        const float* p10 = base + (yc1*DW + xc0)*DD;
        const float* p11 = base + (yc1*DW + xc1)*DD;
        float4 f00 = ld4(p00),     f01 = ld4(p01),     f10 = ld4(p10),     f11 = ld4(p11);
        float4 g00 = ld4(p00+128), g01 = ld4(p01+128), g10 = ld4(p10+128), g11 = ld4(p11+128);

        float4 va, vb;
        va.x = w00*f00.x + w01*f01.x + w10*f10.x + w11*f11.x;
        va.y = w00*f00.y + w01*f01.y + w10*f10.y + w11*f11.y;
        va.z = w00*f00.z + w01*f01.z + w10*f10.z + w11*f11.z;
        va.w = w00*f00.w + w01*f01.w + w10*f10.w + w11*f11.w;
        vb.x = w00*g00.x + w01*g01.x + w10*g10.x + w11*g11.x;
        vb.y = w00*g00.y + w01*g01.y + w10*g10.y + w11*g11.y;
        vb.z = w00*g00.z + w01*g01.z + w10*g10.z + w11*g11.z;
        vb.w = w00*g00.w + w01*g01.w + w10*g10.w + w11*g11.w;
        a0[c] = va; a1[c] = vb;
        sc[c] = va.x*qt0.x + va.y*qt0.y + va.z*qt0.z + va.w*qt0.w
              + vb.x*qt1.x + vb.y*qt1.y + vb.z*qt1.z + vb.w*qt1.w;
    }

#pragma unroll
    for (int c = 0; c < DC; c++) {
        if (!vm[c]) continue;
#pragma unroll
        for (int off = 16; off; off >>= 1)
            sc[c] += __shfl_xor_sync(0xffffffffu, sc[c], off);
    }

    float qb = g_qbk[gw];
    float m = -INFINITY;
#pragma unroll
    for (int c = 0; c < DC; c++) {
        if (vm[c]) { sc[c] = (sc[c] + qb)*0.0625f; m = fmaxf(m, sc[c]); }
    }

    float4 s0 = make_float4(0.f,0.f,0.f,0.f), s1 = make_float4(0.f,0.f,0.f,0.f);
    float Asum = 0.f;
    if (m != -INFINITY) {
        float w[DC];
        float es = 0.f;
#pragma unroll
        for (int c = 0; c < DC; c++) {
            w[c] = 0.f;
            if (vm[c]) { w[c] = expf(sc[c] - m); es += w[c]; }
        }
        float r = 1.f/es;
#pragma unroll
        for (int c = 0; c < DC; c++) {
            if (!vm[c]) continue;
            float at = w[c]*r;
            Asum += at;
            s0.x += at*a0[c].x; s0.y += at*a0[c].y; s0.z += at*a0[c].z; s0.w += at*a0[c].w;
            s1.x += at*a1[c].x; s1.y += at*a1[c].y; s1.z += at*a1[c].z; s1.w += at*a1[c].w;
        }
    }
    float* sp = g_sbar + (size_t)gw*DD;
    *(float4*)(sp + lane*4)       = s0;
    *(float4*)(sp + 128 + lane*4) = s1;
    if (lane == 0) g_asum[gw] = Asum;
}

// ---------------- launch ----------------
extern "C" void kernel_launch(void* const* d_in, const int* in_sizes, int n_in,
                              void* d_out, int out_size)
{
    const float* queries = (const float*)d_in[0];
    const float* feat    = (const float*)d_in[1];
    const float* coords  = (const float*)d_in[2];
    const int*   valid   = (const int*)  d_in[3];
    const float* Wq      = (const float*)d_in[4];
    const float* bq      = (const float*)d_in[5];
    const float* Wkv     = (const float*)d_in[6];
    const float* bkv     = (const float*)d_in[7];
    const float* Wo      = (const float*)d_in[8];
    const float* bo      = (const float*)d_in[9];
    const float* gamma   = (const float*)d_in[10];
    const float* beta    = (const float*)d_in[11];
    float* out = (float*)d_out;

    cudaFuncSetAttribute(k_mma, cudaFuncAttributeMaxDynamicSharedMemorySize, SMEM_MMA);

    k_tr <<<dim3(8,8,4), dim3(32,8)>>>(Wq, Wo, Wkv);
    k_vec<<<3, 256>>>(bq, bkv, Wo);
    k_pre<<<dim3(32,2), 256>>>(Wkv);
    k_ln <<<ROWS/8, 256>>>(queries, gamma, beta);
    k_mma<<<dim3(2, ROWS/128), 256, SMEM_MMA>>>(2, nullptr, nullptr, nullptr);
    k_attn<<<ROWS/8, 256>>>(feat, coords, valid);
    k_mma<<<dim3(2, ROWS/128), 256, SMEM_MMA>>>(3, out, queries, bo);
}

// round 6
// speedup vs baseline: 2.2375x; 1.3587x over previous
#include <cuda_runtime.h>
#include <cuda_bf16.h>
#include <math.h>
#include <stdint.h>

#define DB 2
#define DC 8
#define DN 16384
#define DD 256
#define DH 64
#define DW 64
#define ROWS (DB*DN)

// ---------------- scratch ----------------
__device__ __align__(256) __nv_bfloat16 g_qn_h [ROWS*DD];
__device__ __align__(256) __nv_bfloat16 g_qn_l [ROWS*DD];
__device__ __align__(256) float         g_qt   [ROWS*DD];
__device__ __align__(256) __nv_bfloat16 g_sb_h [ROWS*DD];
__device__ __align__(256) __nv_bfloat16 g_sb_l [ROWS*DD];
__device__ float g_qbk [ROWS];
__device__ float g_asum[ROWS];
__device__ __align__(256) float g_WqT [DD*DD];
__device__ __align__(256) float g_WoT [DD*DD];
__device__ __align__(256) float g_WvT [DD*DD];
__device__ __align__(256) float g_WkT [DD*DD];
__device__ __align__(256) __nv_bfloat16 g_MT_h [DD*DD];
__device__ __align__(256) __nv_bfloat16 g_MT_l [DD*DD];
__device__ __align__(256) __nv_bfloat16 g_W2T_h[DD*DD];
__device__ __align__(256) __nv_bfloat16 g_W2T_l[DD*DD];
__device__ float g_v1 [DD];
__device__ float g_u  [DD];
__device__ float g_wb2[DD];
__device__ float g_c0;

__device__ __forceinline__ float4 ld4(const float* p) { return *(const float4*)p; }

__device__ __forceinline__ void bsplit(float x, __nv_bfloat16& h, __nv_bfloat16& l) {
    h = __float2bfloat16_rn(x);
    l = __float2bfloat16_rn(x - __bfloat162float(h));
}
__device__ __forceinline__ unsigned pk(__nv_bfloat16 a, __nv_bfloat16 b) {
    unsigned short x = *(unsigned short*)&a, y = *(unsigned short*)&b;
    return (unsigned)x | ((unsigned)y << 16);
}

__device__ __forceinline__ uint32_t smem_u32(const void* p) {
    uint32_t a;
    asm("{ .reg .u64 t; cvta.to.shared.u64 t, %1; cvt.u32.u64 %0, t; }" : "=r"(a) : "l"(p));
    return a;
}
__device__ __forceinline__ void cpa16(uint32_t d, const void* s) {
    asm volatile("cp.async.cg.shared.global [%0], [%1], 16;" :: "r"(d), "l"(s));
}

#define LDM4(r, addr) \
    asm volatile("ldmatrix.sync.aligned.m8n8.x4.shared.b16 {%0,%1,%2,%3}, [%4];" \
        : "=r"((r)[0]), "=r"((r)[1]), "=r"((r)[2]), "=r"((r)[3]) : "r"(addr))

#define MMAB(d, a, b0, b1) \
    asm volatile("mma.sync.aligned.m16n8k16.row.col.f32.bf16.bf16.f32 " \
        "{%0,%1,%2,%3}, {%4,%5,%6,%7}, {%8,%9}, {%0,%1,%2,%3};" \
        : "+f"((d)[0]), "+f"((d)[1]), "+f"((d)[2]), "+f"((d)[3]) \
        : "r"((a)[0]), "r"((a)[1]), "r"((a)[2]), "r"((a)[3]), "r"(b0), "r"(b1))

// ---------------- transposes ----------------
__global__ void k_tr(const float* __restrict__ Wq, const float* __restrict__ Wo,
                     const float* __restrict__ Wkv)
{
    __shared__ float t[32][33];
    int z = blockIdx.z;
    const float* src; int ld, off; float* dst;
    if      (z == 0) { src = Wq;  ld = 256; off = 0;   dst = g_WqT; }
    else if (z == 1) { src = Wo;  ld = 256; off = 0;   dst = g_WoT; }
    else if (z == 2) { src = Wkv; ld = 512; off = 256; dst = g_WvT; }
    else             { src = Wkv; ld = 512; off = 0;   dst = g_WkT; }
    int bx = blockIdx.x*32, by = blockIdx.y*32;
    for (int yy = threadIdx.y; yy < 32; yy += 8)
        t[yy][threadIdx.x] = src[(size_t)(by+yy)*ld + off + bx + threadIdx.x];
    __syncthreads();
    for (int yy = threadIdx.y; yy < 32; yy += 8)
        dst[(size_t)(bx+yy)*256 + by + threadIdx.x] = t[threadIdx.x][yy];
}

// ---------------- small vectors ----------------
__global__ void k_vec(const float* __restrict__ bq, const float* __restrict__ bkv,
                      const float* __restrict__ Wo)
{
    int which = blockIdx.x, t = threadIdx.x;
    __shared__ float v[256];
    if      (which == 0) v[t] = bkv[t];
    else if (which == 1) v[t] = bq[t];
    else                 v[t] = bkv[256 + t];
    __syncthreads();
    float acc = 0.f;
    if (which == 0) {
        for (int d = 0; d < 256; d++) acc += g_WqT[d*256 + t] * v[d];
        g_u[t] = acc;
        if (t == 0) { float c = 0.f; for (int d = 0; d < 256; d++) c += bq[d]*bkv[d]; g_c0 = c; }
    } else if (which == 1) {
        for (int d = 0; d < 256; d++) acc += g_WkT[d*256 + t] * v[d];
        g_v1[t] = acc;
    } else {
        for (int f = 0; f < 256; f++) acc += Wo[f*256 + t] * v[f];
        g_wb2[t] = acc;
    }
}

// ---------------- MT[f][e] = Wk@Wq^T ; W2T[t][f] = (Wv@Wo)^T, emit bf16 hi/lo ----------------
__global__ __launch_bounds__(256) void k_pre(const float* __restrict__ Wkv)
{
    __shared__ float Ar[8][256];
    int r0 = blockIdx.x * 8;
    const float* Bsrc; __nv_bfloat16 *Ch, *Cl;
    if (blockIdx.y == 0) {
        for (int i = threadIdx.x; i < 8*256; i += 256) {
            int j = i >> 8, d = i & 255;
            Ar[j][d] = Wkv[(size_t)(r0+j)*512 + d];
        }
        Bsrc = g_WqT; Ch = g_MT_h; Cl = g_MT_l;
    } else {
        for (int i = threadIdx.x; i < 8*256; i += 256) {
            int j = i >> 8, d = i & 255;
            Ar[j][d] = g_WoT[(size_t)(r0+j)*256 + d];
        }
        Bsrc = g_WvT; Ch = g_W2T_h; Cl = g_W2T_l;
    }
    __syncthreads();
    int e = threadIdx.x;
    float acc[8];
#pragma unroll
    for (int j = 0; j < 8; j++) acc[j] = 0.f;
    for (int d = 0; d < 256; d++) {
        float b = Bsrc[(size_t)d*256 + e];
#pragma unroll
        for (int j = 0; j < 8; j++) acc[j] += Ar[j][d] * b;
    }
#pragma unroll
    for (int j = 0; j < 8; j++) {
        __nv_bfloat16 h, l; bsplit(acc[j], h, l);
        Ch[(size_t)(r0+j)*256 + e] = h;
        Cl[(size_t)(r0+j)*256 + e] = l;
    }
}

// ---------------- layernorm + qbk, emits bf16 hi/lo ----------------
__global__ __launch_bounds__(256) void k_ln(const float* __restrict__ q,
                                            const float* __restrict__ gamma,
                                            const float* __restrict__ beta)
{
    int gw   = (blockIdx.x*256 + threadIdx.x) >> 5;
    int lane = threadIdx.x & 31;
    const float* row = q + (size_t)gw*DD;
    float4 x0 = ld4(row + lane*4);
    float4 x1 = ld4(row + 128 + lane*4);
    float s  = x0.x+x0.y+x0.z+x0.w + x1.x+x1.y+x1.z+x1.w;
    float ss = x0.x*x0.x+x0.y*x0.y+x0.z*x0.z+x0.w*x0.w
             + x1.x*x1.x+x1.y*x1.y+x1.z*x1.z+x1.w*x1.w;
#pragma unroll
    for (int off = 16; off; off >>= 1) {
        s  += __shfl_xor_sync(0xffffffffu, s,  off);
        ss += __shfl_xor_sync(0xffffffffu, ss, off);
    }
    float mu   = s * (1.f/DD);
    float var  = ss * (1.f/DD) - mu*mu;
    float rstd = rsqrtf(var + 1e-5f);
    float4 gm0 = ld4(gamma + lane*4), gm1 = ld4(gamma + 128 + lane*4);
    float4 bt0 = ld4(beta  + lane*4), bt1 = ld4(beta  + 128 + lane*4);
    float y[8];
    y[0] = (x0.x-mu)*rstd*gm0.x + bt0.x;  y[1] = (x0.y-mu)*rstd*gm0.y + bt0.y;
    y[2] = (x0.z-mu)*rstd*gm0.z + bt0.z;  y[3] = (x0.w-mu)*rstd*gm0.w + bt0.w;
    y[4] = (x1.x-mu)*rstd*gm1.x + bt1.x;  y[5] = (x1.y-mu)*rstd*gm1.y + bt1.y;
    y[6] = (x1.z-mu)*rstd*gm1.z + bt1.z;  y[7] = (x1.w-mu)*rstd*gm1.w + bt1.w;

    __nv_bfloat16 h[8], l[8];
#pragma unroll
    for (int i = 0; i < 8; i++) bsplit(y[i], h[i], l[i]);
    size_t base = (size_t)gw*DD;
    *(uint2*)(g_qn_h + base + lane*4)       = make_uint2(pk(h[0],h[1]), pk(h[2],h[3]));
    *(uint2*)(g_qn_h + base + 128 + lane*4) = make_uint2(pk(h[4],h[5]), pk(h[6],h[7]));
    *(uint2*)(g_qn_l + base + lane*4)       = make_uint2(pk(l[0],l[1]), pk(l[2],l[3]));
    *(uint2*)(g_qn_l + base + 128 + lane*4) = make_uint2(pk(l[4],l[5]), pk(l[6],l[7]));

    float4 u0 = ld4(g_u + lane*4), u1 = ld4(g_u + 128 + lane*4);
    float p = y[0]*u0.x + y[1]*u0.y + y[2]*u0.z + y[3]*u0.w
            + y[4]*u1.x + y[5]*u1.y + y[6]*u1.z + y[7]*u1.w;
#pragma unroll
    for (int off = 16; off; off >>= 1) p += __shfl_xor_sync(0xffffffffu, p, off);
    if (lane == 0) g_qbk[gw] = p + g_c0;
}

// ================= bf16 3-split mma.sync GEMM with ldmatrix =================
// C[32768,256] = (Ah+Al)[M,K] @ (Bh+Bl)^T, B stored [N][K] k-major bf16.
// CTA 128x128, 8 warps (4x2), warp tile 32x64. K chunks of 32, 3-stage cp.async.
// smem row: 32 K bf16 = 64B data padded to 80B (conflict-free ldmatrix).
#define NCH 8
#define RS 80
#define ARR_B 10240            // 128 rows * 80B
#define STG_BYTES (4*ARR_B)    // Ah, Al, Bh, Bl
#define SMEM_MMA (3*STG_BYTES) // 122880

__device__ __forceinline__ void ld_stage(uint32_t base,
        const __nv_bfloat16* __restrict__ Ah, const __nv_bfloat16* __restrict__ Al,
        const __nv_bfloat16* __restrict__ Bh, const __nv_bfloat16* __restrict__ Bl,
        size_t m0, int n0, int kb, int tid)
{
    for (int i = tid; i < 512; i += 256) {
        int row = i >> 2, slot = i & 3;
        uint32_t off = row*RS + slot*16;
        size_t ga = (m0 + row)*256 + kb + slot*8;
        size_t gb = (size_t)(n0 + row)*256 + kb + slot*8;
        cpa16(base + off,           Ah + ga);
        cpa16(base + ARR_B + off,   Al + ga);
        cpa16(base + 2*ARR_B + off, Bh + gb);
        cpa16(base + 3*ARR_B + off, Bl + gb);
    }
    asm volatile("cp.async.commit_group;");
}

__global__ __launch_bounds__(256, 1) void k_mma(int mode, float* __restrict__ outp,
                                                const float* __restrict__ resid,
                                                const float* __restrict__ bo)
{
    const __nv_bfloat16 *Ah, *Al, *Bh, *Bl; float* C;
    if (mode == 2) { Ah = g_qn_h; Al = g_qn_l; Bh = g_MT_h;  Bl = g_MT_l;  C = g_qt; }
    else           { Ah = g_sb_h; Al = g_sb_l; Bh = g_W2T_h; Bl = g_W2T_l; C = outp; }

    extern __shared__ __align__(16) char smem[];
    uint32_t sb = smem_u32(smem);
    int tid = threadIdx.x, lane = tid & 31, wid = tid >> 5;
    int wm = wid >> 1, wn = wid & 1;
    int qr = lane >> 2, qc = lane & 3;
    size_t m0 = (size_t)blockIdx.y * 128;
    int n0 = blockIdx.x * 128;

    // ldmatrix offsets (stage-relative)
    uint32_t offA[2][2], offB[4][2];
    {
        int arow = lane & 15, asel = lane >> 4;
        int brow = (lane & 7) + ((lane & 16) >> 1);
        int bsel = (lane >> 3) & 1;
#pragma unroll
        for (int ks = 0; ks < 2; ks++) {
#pragma unroll
            for (int mi = 0; mi < 2; mi++)
                offA[mi][ks] = (uint32_t)((wm*32 + mi*16 + arow)*RS + (2*ks + asel)*16);
#pragma unroll
            for (int nip = 0; nip < 4; nip++)
                offB[nip][ks] = (uint32_t)((wn*64 + nip*16 + brow)*RS + (2*ks + bsel)*16);
        }
    }

    float acc[2][8][4];
#pragma unroll
    for (int mi = 0; mi < 2; mi++)
#pragma unroll
        for (int ni = 0; ni < 8; ni++)
#pragma unroll
            for (int t = 0; t < 4; t++) acc[mi][ni][t] = 0.f;

    ld_stage(sb,             Ah, Al, Bh, Bl, m0, n0, 0,  tid);
    ld_stage(sb + STG_BYTES, Ah, Al, Bh, Bl, m0, n0, 32, tid);

    for (int s = 0; s < NCH; s++) {
        if (s == NCH - 1) asm volatile("cp.async.wait_group 0;");
        else              asm volatile("cp.async.wait_group 1;");
        __syncthreads();
        if (s + 2 < NCH)
            ld_stage(sb + ((s + 2) % 3)*STG_BYTES, Ah, Al, Bh, Bl, m0, n0, (s + 2)*32, tid);

        uint32_t st = sb + (s % 3)*STG_BYTES;
#pragma unroll
        for (int ks = 0; ks < 2; ks++) {
            unsigned ra[2][4], la[2][4], rb[4][4], lb[4][4];
#pragma unroll
            for (int mi = 0; mi < 2; mi++) {
                LDM4(ra[mi], st + offA[mi][ks]);
                LDM4(la[mi], st + ARR_B + offA[mi][ks]);
            }
#pragma unroll
            for (int nip = 0; nip < 4; nip++) {
                LDM4(rb[nip], st + 2*ARR_B + offB[nip][ks]);
                LDM4(lb[nip], st + 3*ARR_B + offB[nip][ks]);
            }
            // term hi*hi
#pragma unroll
            for (int mi = 0; mi < 2; mi++)
#pragma unroll
                for (int ni = 0; ni < 8; ni++)
                    MMAB(acc[mi][ni], ra[mi], rb[ni>>1][(ni&1)*2], rb[ni>>1][(ni&1)*2+1]);
            // term hi*lo
#pragma unroll
            for (int mi = 0; mi < 2; mi++)
#pragma unroll
                for (int ni = 0; ni < 8; ni++)
                    MMAB(acc[mi][ni], ra[mi], lb[ni>>1][(ni&1)*2], lb[ni>>1][(ni&1)*2+1]);
            // term lo*hi
#pragma unroll
            for (int mi = 0; mi < 2; mi++)
#pragma unroll
                for (int ni = 0; ni < 8; ni++)
                    MMAB(acc[mi][ni], la[mi], rb[ni>>1][(ni&1)*2], rb[ni>>1][(ni&1)*2+1]);
        }
    }

    // epilogue
#pragma unroll
    for (int mi = 0; mi < 2; mi++) {
        size_t r0 = m0 + wm*32 + mi*16 + qr;
        size_t r1 = r0 + 8;
        float as0 = 0.f, as1 = 0.f;
        if (mode == 3) { as0 = g_asum[r0]; as1 = g_asum[r1]; }
#pragma unroll
        for (int ni = 0; ni < 8; ni++) {
            int c = n0 + wn*64 + ni*8 + qc*2;
            float2 v0 = make_float2(acc[mi][ni][0], acc[mi][ni][1]);
            float2 v1 = make_float2(acc[mi][ni][2], acc[mi][ni][3]);
            if (mode == 2) {
                v0.x += g_v1[c]; v0.y += g_v1[c+1];
                v1.x += g_v1[c]; v1.y += g_v1[c+1];
            } else {
                float2 rs0 = *(const float2*)&resid[r0*256 + c];
                float2 rs1 = *(const float2*)&resid[r1*256 + c];
                float w0 = g_wb2[c], w1 = g_wb2[c+1];
                float b0 = bo[c], b1 = bo[c+1];
                v0.x += rs0.x + as0*w0 + b0;  v0.y += rs0.y + as0*w1 + b1;
                v1.x += rs1.x + as1*w0 + b0;  v1.y += rs1.y + as1*w1 + b1;
            }
            *(float2*)&C[r0*256 + c] = v0;
            *(float2*)&C[r1*256 + c] = v1;
        }
    }
}

// ---------------- fused bilinear gather + scores + softmax + weighted sum ----------------
__global__ __launch_bounds__(256) void k_attn(const float* __restrict__ feat,
                                              const float* __restrict__ coords,
                                              const int*   __restrict__ valid)
{
    int gw   = (blockIdx.x*256 + threadIdx.x) >> 5;
    int lane = threadIdx.x & 31;
    int b = gw >> 14;
    int n = gw & (DN - 1);

    const float* qtp = g_qt + (size_t)gw*DD;
    float4 qt0 = ld4(qtp + lane*4);
    float4 qt1 = ld4(qtp + 128 + lane*4);

    int vm[DC];
#pragma unroll
    for (int c = 0; c < DC; c++)
        vm[c] = valid[(size_t)(b*DC + c)*DN + n];

    float4 a0[DC], a1[DC];
    float  sc[DC];

#pragma unroll
    for (int c = 0; c < DC; c++) {
        sc[c] = -INFINITY;
        if (!vm[c]) continue;          // warp-uniform skip
        int ci = b*DC + c;
        float2 xy = *((const float2*)coords + (size_t)ci*DN + n);
        float x = (xy.x + 1.0f)*0.5f*(float)(DW - 1);
        float y = (xy.y + 1.0f)*0.5f*(float)(DH - 1);
        float x0f = floorf(x), y0f = floorf(y);
        float wx = x - x0f,    wy = y - y0f;
        int x0 = (int)x0f, y0 = (int)y0f;
        int x1 = x0 + 1,   y1 = y0 + 1;
        float w00 = (1.f-wy)*(1.f-wx), w01 = (1.f-wy)*wx;
        float w10 = wy*(1.f-wx),       w11 = wy*wx;
        bool bx0 = (unsigned)x0 < DW, bx1 = (unsigned)x1 < DW;
        bool by0 = (unsigned)y0 < DH, by1 = (unsigned)y1 < DH;
        w00 = (bx0 && by0) ? w00 : 0.f;  w01 = (bx1 && by0) ? w01 : 0.f;
        w10 = (bx0 && by1) ? w10 : 0.f;  w11 = (bx1 && by1) ? w11 : 0.f;
        int xc0 = min(max(x0,0),DW-1), xc1 = min(max(x1,0),DW-1);
        int yc0 = min(max(y0,0),DH-1), yc1 = min(max(y1,0),DH-1);

        const float* base = feat + (size_t)ci*(DH*DW*DD) + lane*4;
        const float* p00 = base + (yc0*DW + xc0)*DD;
        const float* p01 = base + (yc0*DW + xc1)*DD;
        const float* p10 = base + (yc1*DW + xc0)*DD;
        const float* p11 = base + (yc1*DW + xc1)*DD;
        float4 f00 = ld4(p00),     f01 = ld4(p01),     f10 = ld4(p10),     f11 = ld4(p11);
        float4 g00 = ld4(p00+128), g01 = ld4(p01+128), g10 = ld4(p10+128), g11 = ld4(p11+128);

        float4 va, vb;
        va.x = w00*f00.x + w01*f01.x + w10*f10.x + w11*f11.x;
        va.y = w00*f00.y + w01*f01.y + w10*f10.y + w11*f11.y;
        va.z = w00*f00.z + w01*f01.z + w10*f10.z + w11*f11.z;
        va.w = w00*f00.w + w01*f01.w + w10*f10.w + w11*f11.w;
        vb.x = w00*g00.x + w01*g01.x + w10*g10.x + w11*g11.x;
        vb.y = w00*g00.y + w01*g01.y + w10*g10.y + w11*g11.y;
        vb.z = w00*g00.z + w01*g01.z + w10*g10.z + w11*g11.z;
        vb.w = w00*g00.w + w01*g01.w + w10*g10.w + w11*g11.w;
        a0[c] = va; a1[c] = vb;
        sc[c] = va.x*qt0.x + va.y*qt0.y + va.z*qt0.z + va.w*qt0.w
              + vb.x*qt1.x + vb.y*qt1.y + vb.z*qt1.z + vb.w*qt1.w;
    }

#pragma unroll
    for (int c = 0; c < DC; c++) {
        if (!vm[c]) continue;
#pragma unroll
        for (int off = 16; off; off >>= 1)
            sc[c] += __shfl_xor_sync(0xffffffffu, sc[c], off);
    }

    float qb = g_qbk[gw];
    float m = -INFINITY;
#pragma unroll
    for (int c = 0; c < DC; c++) {
        if (vm[c]) { sc[c] = (sc[c] + qb)*0.0625f; m = fmaxf(m, sc[c]); }
    }

    float4 s0 = make_float4(0.f,0.f,0.f,0.f), s1 = make_float4(0.f,0.f,0.f,0.f);
    float Asum = 0.f;
    if (m != -INFINITY) {
        float w[DC];
        float es = 0.f;
#pragma unroll
        for (int c = 0; c < DC; c++) {
            w[c] = 0.f;
            if (vm[c]) { w[c] = expf(sc[c] - m); es += w[c]; }
        }
        float r = 1.f/es;
#pragma unroll
        for (int c = 0; c < DC; c++) {
            if (!vm[c]) continue;
            float at = w[c]*r;
            Asum += at;
            s0.x += at*a0[c].x; s0.y += at*a0[c].y; s0.z += at*a0[c].z; s0.w += at*a0[c].w;
            s1.x += at*a1[c].x; s1.y += at*a1[c].y; s1.z += at*a1[c].z; s1.w += at*a1[c].w;
        }
    }
    float v[8] = {s0.x,s0.y,s0.z,s0.w,s1.x,s1.y,s1.z,s1.w};
    __nv_bfloat16 h[8], l[8];
#pragma unroll
    for (int i = 0; i < 8; i++) bsplit(v[i], h[i], l[i]);
    size_t base2 = (size_t)gw*DD;
    *(uint2*)(g_sb_h + base2 + lane*4)       = make_uint2(pk(h[0],h[1]), pk(h[2],h[3]));
    *(uint2*)(g_sb_h + base2 + 128 + lane*4) = make_uint2(pk(h[4],h[5]), pk(h[6],h[7]));
    *(uint2*)(g_sb_l + base2 + lane*4)       = make_uint2(pk(l[0],l[1]), pk(l[2],l[3]));
    *(uint2*)(g_sb_l + base2 + 128 + lane*4) = make_uint2(pk(l[4],l[5]), pk(l[6],l[7]));
    if (lane == 0) g_asum[gw] = Asum;
}

// ---------------- launch ----------------
extern "C" void kernel_launch(void* const* d_in, const int* in_sizes, int n_in,
                              void* d_out, int out_size)
{
    const float* queries = (const float*)d_in[0];
    const float* feat    = (const float*)d_in[1];
    const float* coords  = (const float*)d_in[2];
    const int*   valid   = (const int*)  d_in[3];
    const float* Wq      = (const float*)d_in[4];
    const float* bq      = (const float*)d_in[5];
    const float* Wkv     = (const float*)d_in[6];
    const float* bkv     = (const float*)d_in[7];
    const float* Wo      = (const float*)d_in[8];
    const float* bo      = (const float*)d_in[9];
    const float* gamma   = (const float*)d_in[10];
    const float* beta    = (const float*)d_in[11];
    float* out = (float*)d_out;

    cudaFuncSetAttribute(k_mma, cudaFuncAttributeMaxDynamicSharedMemorySize, SMEM_MMA);

    k_tr <<<dim3(8,8,4), dim3(32,8)>>>(Wq, Wo, Wkv);
    k_vec<<<3, 256>>>(bq, bkv, Wo);
    k_pre<<<dim3(32,2), 256>>>(Wkv);
    k_ln <<<ROWS/8, 256>>>(queries, gamma, beta);
    k_mma<<<dim3(2, ROWS/128), 256, SMEM_MMA>>>(2, nullptr, nullptr, nullptr);
    k_attn<<<ROWS/8, 256>>>(feat, coords, valid);
    k_mma<<<dim3(2, ROWS/128), 256, SMEM_MMA>>>(3, out, queries, bo);
}